// round 17
// baseline (speedup 1.0000x reference)
#include <cuda_runtime.h>

#define BB     32
#define SS     512
#define HH     768
#define NC     32
#define MHL    16
#define H4     (HH / 4)       // 192 float4 per row
#define CPL    6              // float4 chunks per lane
#define TPB    256            // 8 warps
#define GRID   592            // 4 CTAs/SM * 148 SMs, one exact wave
#define NWARPS (GRID * (TPB / 32))   // 4736
#define NROWS  (BB * SS)      // 16384
#define NCOMB  (2 * 11 * 6)   // 132
#define COMB_ELEMS (NCOMB * H4)      // 25344 float4

__device__ float4 g_comb[COMB_ELEMS];

__global__ __launch_bounds__(256)
void build_comb_kernel(const float4* __restrict__ tok_type_emb,
                       const float4* __restrict__ match_emb,
                       const float4* __restrict__ type_emb)
{
    // grid-stride over all 25344 elements; wide wave, latency overlapped
    for (int idx = blockIdx.x * blockDim.x + threadIdx.x;
         idx < COMB_ELEMS; idx += gridDim.x * blockDim.x) {
        const int combo = idx / H4;
        const int col   = idx - combo * H4;
        const int tt  = combo / 66;
        const int rem = combo % 66;
        const int mt  = rem / 6;
        const int ty  = rem % 6;
        const float4 a = tok_type_emb[tt * H4 + col];
        const float4 b = match_emb[mt * H4 + col];
        const float4 c = type_emb[ty * H4 + col];
        float4 r;
        r.x = a.x + b.x + c.x;
        r.y = a.y + b.y + c.y;
        r.z = a.z + b.z + c.z;
        r.w = a.w + b.w + c.w;
        g_comb[idx] = r;
    }
}

__global__ __launch_bounds__(TPB, 4)
void bert_emb_kernel(
    const int*    __restrict__ input_ids,       // [B,S]
    const int*    __restrict__ header_ids,      // [B,NC,MHL]
    const int*    __restrict__ token_type_ids,  // [B,S]
    const int*    __restrict__ match_type_ids,  // [B,S]
    const int*    __restrict__ type_idx,        // [B,S]
    const int*    __restrict__ col_pos,         // [B,NC]
    const int*    __restrict__ col_idx,         // [B,NC]
    const int*    __restrict__ header_len,      // [B,NC]
    const float4* __restrict__ word_emb,        // [VOCAB,H4]
    const float4* __restrict__ pos_emb,         // [MAX_POS,H4]
    const float4* __restrict__ ln_w,            // [H4]
    const float4* __restrict__ ln_b,            // [H4]
    float4*       __restrict__ out)             // [B,S,H4]
{
    const int tid  = threadIdx.x;
    const int warp = tid >> 5;
    const int lane = tid & 31;

    __shared__ float4 sgw[H4];
    __shared__ float4 sgb[H4];
    if (tid < H4) {
        sgw[tid] = ln_w[tid];
        sgb[tid] = ln_b[tid];
    }
    __syncthreads();

    // balanced contiguous chunk for this warp: 3 or 4 rows
    const int g      = blockIdx.x * (TPB / 32) + warp;
    const int rstart = (int)(((long long)g * NROWS) / NWARPS);
    const int rend   = (int)(((long long)(g + 1) * NROWS) / NWARPS);

    // hoisted per-batch metadata (reloaded only on batch-boundary crossing)
    int bcur = rstart >> 9;
    int cp = col_pos[bcur * NC + lane];
    int ci = col_idx[bcur * NC + lane];
    int hl = header_len[bcur * NC + lane];

    #pragma unroll 1
    for (int row = rstart; row < rend; ++row) {
        const int b = row >> 9;
        const int s = row & (SS - 1);

        if (b != bcur) {
            bcur = b;
            cp = col_pos[b * NC + lane];
            ci = col_idx[b * NC + lane];
            hl = header_len[b * NC + lane];
        }

        // ---- scatter detection (register-only) ----
        const unsigned mm = __ballot_sync(0xffffffffu, cp == s);
        int len = 0, cidx = 0;
        if (mm) {
            const int c = __ffs(mm) - 1;
            cidx = __shfl_sync(0xffffffffu, ci, c);
            len  = __shfl_sync(0xffffffffu, hl, cidx);
        }

        // scalar indices (kept in regs for both passes)
        const int wid   = input_ids[row];
        const int combo = token_type_ids[row] * 66
                        + match_type_ids[row] * 6
                        + type_idx[row];

        const size_t wbase = (size_t)wid * H4 + lane;
        const size_t pbase = (size_t)s * H4 + lane;
        const size_t cbase = (size_t)combo * H4 + lane;
        const int* hids = header_ids + (b * NC + cidx) * MHL;
        const float inv = (len > 0) ? (1.0f / (float)len) : 0.0f;

        // ================= PASS 1: stats only, no stored vector =============
        float sum = 0.f, sq = 0.f;
        if (len == 0) {
            #pragma unroll 3
            for (int k = 0; k < CPL; ++k) {
                const float4 w  = word_emb[wbase + k * 32];
                const float4 pe = pos_emb[pbase + k * 32];
                const float4 cb = g_comb[cbase + k * 32];
                const float ex = w.x + pe.x + cb.x;
                const float ey = w.y + pe.y + cb.y;
                const float ez = w.z + pe.z + cb.z;
                const float ew = w.w + pe.w + cb.w;
                sum += ex + ey + ez + ew;
                sq  += ex * ex + ey * ey + ez * ez + ew * ew;
            }
        } else {
            #pragma unroll 1
            for (int k = 0; k < CPL; ++k) {
                float ax = 0.f, ay = 0.f, az = 0.f, aw = 0.f;
                for (int l = 0; l < len; ++l) {
                    const float4 w = word_emb[(size_t)hids[l] * H4 + lane + k * 32];
                    ax += w.x; ay += w.y; az += w.z; aw += w.w;
                }
                const float4 pe = pos_emb[pbase + k * 32];
                const float4 cb = g_comb[cbase + k * 32];
                const float ex = ax * inv + pe.x + cb.x;
                const float ey = ay * inv + pe.y + cb.y;
                const float ez = az * inv + pe.z + cb.z;
                const float ew = aw * inv + pe.w + cb.w;
                sum += ex + ey + ez + ew;
                sq  += ex * ex + ey * ey + ez * ez + ew * ew;
            }
        }

        #pragma unroll
        for (int o = 16; o > 0; o >>= 1) {
            sum += __shfl_xor_sync(0xffffffffu, sum, o);
            sq  += __shfl_xor_sync(0xffffffffu, sq,  o);
        }
        const float mean = sum * (1.0f / HH);
        float var = fmaxf(sq * (1.0f / HH) - mean * mean, 0.0f);
        const float rstd = rsqrtf(var + 1e-12f);

        // ================= PASS 2: reload (L1-hot), normalize, store ========
        float4* orow = out + (size_t)row * H4 + lane;
        if (len == 0) {
            #pragma unroll 3
            for (int k = 0; k < CPL; ++k) {
                const float4 w  = word_emb[wbase + k * 32];
                const float4 pe = pos_emb[pbase + k * 32];
                const float4 cb = g_comb[cbase + k * 32];
                const float4 gwv = sgw[lane + k * 32];
                const float4 gbv = sgb[lane + k * 32];
                float4 o;
                o.x = (w.x + pe.x + cb.x - mean) * rstd * gwv.x + gbv.x;
                o.y = (w.y + pe.y + cb.y - mean) * rstd * gwv.y + gbv.y;
                o.z = (w.z + pe.z + cb.z - mean) * rstd * gwv.z + gbv.z;
                o.w = (w.w + pe.w + cb.w - mean) * rstd * gwv.w + gbv.w;
                __stcs(orow + k * 32, o);
            }
        } else {
            #pragma unroll 1
            for (int k = 0; k < CPL; ++k) {
                float ax = 0.f, ay = 0.f, az = 0.f, aw = 0.f;
                for (int l = 0; l < len; ++l) {
                    const float4 w = word_emb[(size_t)hids[l] * H4 + lane + k * 32];
                    ax += w.x; ay += w.y; az += w.z; aw += w.w;
                }
                const float4 pe = pos_emb[pbase + k * 32];
                const float4 cb = g_comb[cbase + k * 32];
                const float4 gwv = sgw[lane + k * 32];
                const float4 gbv = sgb[lane + k * 32];
                float4 o;
                o.x = (ax * inv + pe.x + cb.x - mean) * rstd * gwv.x + gbv.x;
                o.y = (ay * inv + pe.y + cb.y - mean) * rstd * gwv.y + gbv.y;
                o.z = (az * inv + pe.z + cb.z - mean) * rstd * gwv.z + gbv.z;
                o.w = (aw * inv + pe.w + cb.w - mean) * rstd * gwv.w + gbv.w;
                __stcs(orow + k * 32, o);
            }
        }
    }
}

extern "C" void kernel_launch(void* const* d_in, const int* in_sizes, int n_in,
                              void* d_out, int out_size) {
    (void)in_sizes; (void)n_in; (void)out_size;
    const int*    input_ids       = (const int*)   d_in[0];
    const int*    header_ids      = (const int*)   d_in[1];
    const int*    token_type_ids  = (const int*)   d_in[2];
    const int*    match_type_ids  = (const int*)   d_in[3];
    const int*    type_idx        = (const int*)   d_in[4];
    const int*    col_pos         = (const int*)   d_in[5];
    const int*    col_idx         = (const int*)   d_in[6];
    const int*    header_len      = (const int*)   d_in[7];
    const float4* word_emb        = (const float4*)d_in[8];
    const float4* pos_emb         = (const float4*)d_in[9];
    const float4* tok_type_emb    = (const float4*)d_in[10];
    const float4* match_emb       = (const float4*)d_in[11];
    const float4* type_emb        = (const float4*)d_in[12];
    const float4* ln_w            = (const float4*)d_in[13];
    const float4* ln_b            = (const float4*)d_in[14];
    float4*       out             = (float4*)d_out;

    build_comb_kernel<<<148, 256>>>(tok_type_emb, match_emb, type_emb);

    bert_emb_kernel<<<GRID, TPB>>>(
        input_ids, header_ids, token_type_ids, match_type_ids, type_idx,
        col_pos, col_idx, header_len, word_emb, pos_emb, ln_w, ln_b, out);
}